// round 2
// baseline (speedup 1.0000x reference)
#include <cuda_runtime.h>
#include <cstdint>

#define D      256
#define NPTS   16384
#define KCODES 8192
#define BM     64
#define BN     128
#define TM     8
#define TN     4

// scratch (static device globals: allowed; no runtime allocation)
__device__ float g_zt[D * NPTS];     // [d][n]
__device__ float g_cbt[D * KCODES];  // [d][k]
__device__ float g_z2[NPTS];         // sum z^2 per point, strict sequential order
__device__ int   g_idx[NPTS];

// ---------------- z transpose: NCHW [16][256][1024] -> [d][n], n = b*1024+hw
__global__ void k_zt(const float* __restrict__ ze) {
    int i = blockIdx.x * 256 + threadIdx.x;
    int d  = i >> 14;
    int r  = i & (NPTS - 1);
    int b  = r >> 10;
    int hw = r & 1023;
    g_zt[i] = ze[((b << 8) + d) * 1024 + hw];
}

// ---------------- codebook transpose: [k][d] -> [d][k]
__global__ void k_cbt(const float* __restrict__ cb) {
    __shared__ float t[32][33];
    int k0 = blockIdx.x * 32;
    int d0 = blockIdx.y * 32;
    int tx = threadIdx.x, ty = threadIdx.y;            // 32 x 8
#pragma unroll
    for (int i = 0; i < 4; i++)
        t[ty + 8 * i][tx] = cb[(k0 + ty + 8 * i) * D + d0 + tx];
    __syncthreads();
#pragma unroll
    for (int i = 0; i < 4; i++)
        g_cbt[(d0 + ty + 8 * i) * KCODES + k0 + tx] = t[tx][ty + 8 * i];
}

// ---------------- z2: strict sequential fl(s + fl(z*z)), d = 0..255
__global__ void k_z2() {
    int n = blockIdx.x * 256 + threadIdx.x;
    float s = 0.f;
    for (int d = 0; d < D; d++) {
        float v = g_zt[d * NPTS + n];
        s = __fadd_rn(s, __fmul_rn(v, v));
    }
    g_z2[n] = s;
}

// ---------------- main: sequential-fma dot + quantized dist + first-index argmin
__global__ __launch_bounds__(256) void k_main(float* __restrict__ out_idxf) {
    extern __shared__ char smem[];
    float* As = (float*)smem;                         // [256][64]  64KB
    float* Bs = (float*)(smem + D * BM * 4);          // [2][32][128] 32KB

    const int tid = threadIdx.x;
    const int tm  = tid >> 5;    // warp id 0..7 -> row group
    const int tn  = tid & 31;    // lane -> code group
    const int n0  = blockIdx.x * BM;

    for (int j = tid; j < D * BM; j += 256) {
        int d = j >> 6;
        int r = j & (BM - 1);
        As[j] = g_zt[d * NPTS + n0 + r];
    }

    float z2r[TM];
#pragma unroll
    for (int i = 0; i < TM; i++) z2r[i] = g_z2[n0 + tm * TM + i];

    float bestd[TM];
    int   bidx[TM];
#pragma unroll
    for (int i = 0; i < TM; i++) { bestd[i] = 3.4e38f; bidx[i] = 0x7fffffff; }

    for (int kt = 0; kt < KCODES / BN; kt++) {
        const int k0 = kt * BN;

        __syncthreads();
        // stage 0 load: d rows [0,32) of this k-tile
#pragma unroll
        for (int it = 0; it < 4; it++) {
            int j  = tid + it * 256;           // 0..1023
            int c4 = j & 31;
            int dl = j >> 5;
            float4 v = *(const float4*)&g_cbt[(size_t)dl * KCODES + k0 + c4 * 4];
            *(float4*)&Bs[dl * BN + c4 * 4] = v;
        }
        __syncthreads();

        float acc[TM][TN];
#pragma unroll
        for (int i = 0; i < TM; i++)
#pragma unroll
            for (int j = 0; j < TN; j++) acc[i][j] = 0.f;

#pragma unroll 1
        for (int s = 0; s < 8; s++) {
            const int cur = s & 1;
            float4 pf[4];
            if (s < 7) {
#pragma unroll
                for (int it = 0; it < 4; it++) {
                    int j  = tid + it * 256;
                    int c4 = j & 31;
                    int dl = j >> 5;
                    pf[it] = *(const float4*)&g_cbt[(size_t)((s + 1) * 32 + dl) * KCODES + k0 + c4 * 4];
                }
            }
            // strict d-ascending accumulation: d = s*32 + dl2
#pragma unroll
            for (int dl2 = 0; dl2 < 32; dl2++) {
                const float* arow = &As[(s * 32 + dl2) * BM + tm * TM];
                float4 a0 = *(const float4*)(arow);
                float4 a1 = *(const float4*)(arow + 4);
                float4 b  = *(const float4*)&Bs[cur * 32 * BN + dl2 * BN + tn * TN];
                float a[TM] = {a0.x, a0.y, a0.z, a0.w, a1.x, a1.y, a1.z, a1.w};
                float bb[TN] = {b.x, b.y, b.z, b.w};
#pragma unroll
                for (int i = 0; i < TM; i++)
#pragma unroll
                    for (int j = 0; j < TN; j++)
                        acc[i][j] = __fmaf_rn(a[i], bb[j], acc[i][j]);
            }
            if (s < 7) {
                const int nxt = cur ^ 1;
#pragma unroll
                for (int it = 0; it < 4; it++) {
                    int j  = tid + it * 256;
                    int c4 = j & 31;
                    int dl = j >> 5;
                    *(float4*)&Bs[nxt * 32 * BN + dl * BN + c4 * 4] = pf[it];
                }
            }
            __syncthreads();
        }

        // dist = fl(z2 - 2*dot)  (2*dot exact; +c2 provably a no-op at this scale)
#pragma unroll
        for (int j = 0; j < TN; j++) {
            int cid = k0 + tn * TN + j;
#pragma unroll
            for (int i = 0; i < TM; i++) {
                float t  = __fmul_rn(2.0f, acc[i][j]);
                float dd = __fsub_rn(z2r[i], t);
                if (dd < bestd[i] || (dd == bestd[i] && cid < bidx[i])) {
                    bestd[i] = dd;
                    bidx[i]  = cid;
                }
            }
        }
    }

    // warp argmin reduce, tie -> lower index (associative, matches jnp.argmin)
#pragma unroll
    for (int i = 0; i < TM; i++) {
        float v  = bestd[i];
        int   ix = bidx[i];
#pragma unroll
        for (int off = 16; off; off >>= 1) {
            float v2 = __shfl_xor_sync(0xffffffffu, v, off);
            int   i2 = __shfl_xor_sync(0xffffffffu, ix, off);
            if (v2 < v || (v2 == v && i2 < ix)) { v = v2; ix = i2; }
        }
        if (tn == 0) {
            int row = n0 + tm * TM + i;
            g_idx[row]    = ix;
            out_idxf[row] = (float)ix;
        }
    }
}

// ---------------- gather + straight-through rounding, NCHW output
__global__ void k_gather(const float* __restrict__ ze,
                         const float* __restrict__ cb,
                         float* __restrict__ out) {
    __shared__ int   sidx[32];
    __shared__ float cbs[D][33];
    int nb  = blockIdx.x;
    int b   = nb >> 5;
    int hw0 = (nb & 31) << 5;
    int tid = threadIdx.x;
    if (tid < 32) sidx[tid] = g_idx[b * 1024 + hw0 + tid];
    __syncthreads();
    for (int j = tid; j < 32 * 64; j += 256) {
        int r  = j >> 6;
        int f4 = j & 63;
        float4 v = *(const float4*)&cb[(size_t)sidx[r] * D + f4 * 4];
        cbs[f4 * 4 + 0][r] = v.x;
        cbs[f4 * 4 + 1][r] = v.y;
        cbs[f4 * 4 + 2][r] = v.z;
        cbs[f4 * 4 + 3][r] = v.w;
    }
    __syncthreads();
    for (int i = tid; i < 32 * D; i += 256) {
        int d = i >> 5;
        int w = i & 31;
        int gi = ((b << 8) + d) * 1024 + hw0 + w;
        float z = ze[gi];
        // replicate reference STE rounding exactly: z + (z_q - z)
        out[gi] = __fadd_rn(z, __fsub_rn(cbs[d][w], z));
    }
}

extern "C" void kernel_launch(void* const* d_in, const int* in_sizes, int n_in,
                              void* d_out, int out_size) {
    const float* ze = (const float*)d_in[0];
    const float* cb = (const float*)d_in[1];
    float* out = (float*)d_out;

    cudaFuncSetAttribute(k_main, cudaFuncAttributeMaxDynamicSharedMemorySize, 98304);

    k_zt<<<(D * NPTS) / 256, 256>>>(ze);
    k_cbt<<<dim3(KCODES / 32, D / 32), dim3(32, 8)>>>(cb);
    k_z2<<<NPTS / 256, 256>>>();
    k_main<<<NPTS / BM, 256, 98304>>>(out + (size_t)D * NPTS);
    k_gather<<<NPTS / 32, 256>>>(ze, cb, out);
}

// round 3
// speedup vs baseline: 1.1573x; 1.1573x over previous
#include <cuda_runtime.h>
#include <cstdint>

#define D      256
#define NPTS   16384
#define KCODES 8192
#define BM     64
#define BN     128
#define TMP    4   // row PAIRS per thread (8 rows)
#define TN     4   // codes per thread

// scratch (static device globals: allowed; no runtime allocation)
__device__ float g_zt[D * NPTS];     // [d][n]
__device__ float g_cbt[D * KCODES];  // [d][k]
__device__ float g_z2[NPTS];         // sum z^2 per point, strict sequential order
__device__ int   g_idx[NPTS];

union F2U { unsigned long long u; float2 f; };

// packed dual-fma: each 32-bit half is an independent fp32 fma.rn — numerics
// identical to scalar __fmaf_rn per half.
__device__ __forceinline__ unsigned long long ffma2(unsigned long long a,
                                                    unsigned long long b,
                                                    unsigned long long c) {
    unsigned long long d;
    asm("fma.rn.f32x2 %0, %1, %2, %3;" : "=l"(d) : "l"(a), "l"(b), "l"(c));
    return d;
}

__device__ __forceinline__ unsigned long long dup2(float v) {
    unsigned long long r;
    asm("mov.b64 %0, {%1, %1};" : "=l"(r) : "r"(__float_as_uint(v)));
    return r;
}

// ---------------- z transpose: NCHW [16][256][1024] -> [d][n], n = b*1024+hw
__global__ void k_zt(const float* __restrict__ ze) {
    int i = blockIdx.x * 256 + threadIdx.x;
    int d  = i >> 14;
    int r  = i & (NPTS - 1);
    int b  = r >> 10;
    int hw = r & 1023;
    g_zt[i] = ze[((b << 8) + d) * 1024 + hw];
}

// ---------------- codebook transpose: [k][d] -> [d][k]
__global__ void k_cbt(const float* __restrict__ cb) {
    __shared__ float t[32][33];
    int k0 = blockIdx.x * 32;
    int d0 = blockIdx.y * 32;
    int tx = threadIdx.x, ty = threadIdx.y;            // 32 x 8
#pragma unroll
    for (int i = 0; i < 4; i++)
        t[ty + 8 * i][tx] = cb[(k0 + ty + 8 * i) * D + d0 + tx];
    __syncthreads();
#pragma unroll
    for (int i = 0; i < 4; i++)
        g_cbt[(d0 + ty + 8 * i) * KCODES + k0 + tx] = t[tx][ty + 8 * i];
}

// ---------------- z2: strict sequential fl(s + fl(z*z)), d = 0..255
__global__ void k_z2() {
    int n = blockIdx.x * 256 + threadIdx.x;
    float s = 0.f;
    for (int d = 0; d < D; d++) {
        float v = g_zt[d * NPTS + n];
        s = __fadd_rn(s, __fmul_rn(v, v));
    }
    g_z2[n] = s;
}

// ---------------- main: FFMA2 (rows paired) + quantized dist + first-index argmin
__global__ __launch_bounds__(256, 2) void k_main(float* __restrict__ out_idxf) {
    extern __shared__ char smem[];
    float* As = (float*)smem;                         // [256][64]  64KB
    float* Bs = (float*)(smem + D * BM * 4);          // [2][32][128] 32KB

    const int tid = threadIdx.x;
    const int tm  = tid >> 5;    // warp id 0..7 -> row group (8 rows)
    const int tn  = tid & 31;    // lane -> code group (4 codes)
    const int n0  = blockIdx.x * BM;

    for (int j = tid; j < D * BM; j += 256) {
        int d = j >> 6;
        int r = j & (BM - 1);
        As[j] = g_zt[d * NPTS + n0 + r];
    }

    float z2r[2 * TMP];
#pragma unroll
    for (int i = 0; i < 2 * TMP; i++) z2r[i] = g_z2[n0 + tm * 8 + i];

    float bestd[2 * TMP];
    int   bidx[2 * TMP];
#pragma unroll
    for (int i = 0; i < 2 * TMP; i++) { bestd[i] = 3.4e38f; bidx[i] = 0x7fffffff; }

    for (int kt = 0; kt < KCODES / BN; kt++) {
        const int k0 = kt * BN;

        __syncthreads();
        // stage 0 load: d rows [0,32) of this k-tile
#pragma unroll
        for (int it = 0; it < 4; it++) {
            int j  = tid + it * 256;           // 0..1023
            int c4 = j & 31;
            int dl = j >> 5;
            float4 v = *(const float4*)&g_cbt[(size_t)dl * KCODES + k0 + c4 * 4];
            *(float4*)&Bs[dl * BN + c4 * 4] = v;
        }
        __syncthreads();

        // acc[i][j]: rows (tm*8+2i, tm*8+2i+1) x code (k0+tn*4+j), halves independent
        unsigned long long acc[TMP][TN];
#pragma unroll
        for (int i = 0; i < TMP; i++)
#pragma unroll
            for (int j = 0; j < TN; j++) acc[i][j] = 0ull;

#pragma unroll 1
        for (int s = 0; s < 8; s++) {
            const int cur = s & 1;
            float4 pf[4];
            if (s < 7) {
#pragma unroll
                for (int it = 0; it < 4; it++) {
                    int j  = tid + it * 256;
                    int c4 = j & 31;
                    int dl = j >> 5;
                    pf[it] = *(const float4*)&g_cbt[(size_t)((s + 1) * 32 + dl) * KCODES + k0 + c4 * 4];
                }
            }
            // strict d-ascending accumulation: d = s*32 + dl2
#pragma unroll
            for (int dl2 = 0; dl2 < 32; dl2++) {
                const float* arow = &As[(s * 32 + dl2) * BM + tm * 8];
                // row pairs straight from smem: (r0,r1)(r2,r3)(r4,r5)(r6,r7)
                ulonglong2 t0 = *((const ulonglong2*)arow + 0);
                ulonglong2 t1 = *((const ulonglong2*)arow + 1);
                unsigned long long a[TMP] = {t0.x, t0.y, t1.x, t1.y};
                float4 b = *(const float4*)&Bs[cur * 32 * BN + dl2 * BN + tn * TN];
                unsigned long long bd[TN] = {dup2(b.x), dup2(b.y), dup2(b.z), dup2(b.w)};
#pragma unroll
                for (int i = 0; i < TMP; i++)
#pragma unroll
                    for (int j = 0; j < TN; j++)
                        acc[i][j] = ffma2(a[i], bd[j], acc[i][j]);
            }
            if (s < 7) {
                const int nxt = cur ^ 1;
#pragma unroll
                for (int it = 0; it < 4; it++) {
                    int j  = tid + it * 256;
                    int c4 = j & 31;
                    int dl = j >> 5;
                    *(float4*)&Bs[nxt * 32 * BN + dl * BN + c4 * 4] = pf[it];
                }
            }
            __syncthreads();
        }

        // dist = fl(z2 - 2*dot)  (2*dot exact; +c2 provably a no-op at this scale)
#pragma unroll
        for (int j = 0; j < TN; j++) {
            int cid = k0 + tn * TN + j;
#pragma unroll
            for (int i = 0; i < TMP; i++) {
                F2U u; u.u = acc[i][j];
                float d0v = __fsub_rn(z2r[2 * i],     __fmul_rn(2.0f, u.f.x));
                float d1v = __fsub_rn(z2r[2 * i + 1], __fmul_rn(2.0f, u.f.y));
                if (d0v < bestd[2 * i] || (d0v == bestd[2 * i] && cid < bidx[2 * i])) {
                    bestd[2 * i] = d0v; bidx[2 * i] = cid;
                }
                if (d1v < bestd[2 * i + 1] || (d1v == bestd[2 * i + 1] && cid < bidx[2 * i + 1])) {
                    bestd[2 * i + 1] = d1v; bidx[2 * i + 1] = cid;
                }
            }
        }
    }

    // warp argmin reduce, tie -> lower index (associative, matches jnp.argmin)
#pragma unroll
    for (int i = 0; i < 2 * TMP; i++) {
        float v  = bestd[i];
        int   ix = bidx[i];
#pragma unroll
        for (int off = 16; off; off >>= 1) {
            float v2 = __shfl_xor_sync(0xffffffffu, v, off);
            int   i2 = __shfl_xor_sync(0xffffffffu, ix, off);
            if (v2 < v || (v2 == v && i2 < ix)) { v = v2; ix = i2; }
        }
        if (tn == 0) {
            int row = n0 + tm * 8 + i;
            g_idx[row]    = ix;
            out_idxf[row] = (float)ix;
        }
    }
}

// ---------------- gather + straight-through rounding, NCHW output
__global__ void k_gather(const float* __restrict__ ze,
                         const float* __restrict__ cb,
                         float* __restrict__ out) {
    __shared__ int   sidx[32];
    __shared__ float cbs[D][33];
    int nb  = blockIdx.x;
    int b   = nb >> 5;
    int hw0 = (nb & 31) << 5;
    int tid = threadIdx.x;
    if (tid < 32) sidx[tid] = g_idx[b * 1024 + hw0 + tid];
    __syncthreads();
    for (int j = tid; j < 32 * 64; j += 256) {
        int r  = j >> 6;
        int f4 = j & 63;
        float4 v = *(const float4*)&cb[(size_t)sidx[r] * D + f4 * 4];
        cbs[f4 * 4 + 0][r] = v.x;
        cbs[f4 * 4 + 1][r] = v.y;
        cbs[f4 * 4 + 2][r] = v.z;
        cbs[f4 * 4 + 3][r] = v.w;
    }
    __syncthreads();
    for (int i = tid; i < 32 * D; i += 256) {
        int d = i >> 5;
        int w = i & 31;
        int gi = ((b << 8) + d) * 1024 + hw0 + w;
        float z = ze[gi];
        // replicate reference STE rounding exactly: z + (z_q - z)
        out[gi] = __fadd_rn(z, __fsub_rn(cbs[d][w], z));
    }
}

extern "C" void kernel_launch(void* const* d_in, const int* in_sizes, int n_in,
                              void* d_out, int out_size) {
    const float* ze = (const float*)d_in[0];
    const float* cb = (const float*)d_in[1];
    float* out = (float*)d_out;

    cudaFuncSetAttribute(k_main, cudaFuncAttributeMaxDynamicSharedMemorySize, 98304);

    k_zt<<<(D * NPTS) / 256, 256>>>(ze);
    k_cbt<<<dim3(KCODES / 32, D / 32), dim3(32, 8)>>>(cb);
    k_z2<<<NPTS / 256, 256>>>();
    k_main<<<NPTS / BM, 256, 98304>>>(out + (size_t)D * NPTS);
    k_gather<<<NPTS / 32, 256>>>(ze, cb, out);
}